// round 9
// baseline (speedup 1.0000x reference)
#include <cuda_runtime.h>
#include <cuda_bf16.h>
#include <math.h>
#include <stdint.h>

// ---------------------------------------------------------------------------
// WindowAttention: tf32 tensor-core GEMMs + tensor-core attention
// ---------------------------------------------------------------------------

#define BW      4096
#define NTOK    49
#define DIM     384
#define NHEAD   12
#define HD      32
#define NW      256
#define M_ROWS  (BW * NTOK)        // 200704
#define QKV_N   (3 * DIM)          // 1152

__device__ float g_qkv[(size_t)M_ROWS * QKV_N];   // ~925 MB
__device__ float g_att[(size_t)M_ROWS * DIM];     // ~308 MB

__device__ __forceinline__ float f2tf(float x) {
    uint32_t r;
    asm("cvt.rna.tf32.f32 %0, %1;" : "=r"(r) : "f"(x));
    return __uint_as_float(r);
}

// ---------------------------------------------------------------------------
// tf32 tensor-core GEMM: C[M,N] = A[M,K] @ B[K,N] + bias[N]
// 128x128x32 tile, 256 threads, warp tile 64x32, double-buffered smem.
// __launch_bounds__(256,2) caps regs at 128 -> 2 blocks/SM (was 1 at 134 regs).
// ---------------------------------------------------------------------------
#define ASTR 36
#define SMEM_BYTES (2 * 128 * ASTR * 4 * 2)   // 73728

__global__ __launch_bounds__(256, 2)
void tf32_gemm_bias(const float* __restrict__ A, const float* __restrict__ B,
                    const float* __restrict__ bias, float* __restrict__ C,
                    int M, int N, int K)
{
    const int tid  = threadIdx.x;
    const int lane = tid & 31;
    const int wid  = tid >> 5;
    const int warpM = wid & 1;
    const int warpN = wid >> 1;
    const int g   = lane >> 2;
    const int tig = lane & 3;

    const int bn = blockIdx.x * 128;
    const int bm = blockIdx.y * 128;

    extern __shared__ float sm[];
    float* As = sm;
    float* Bs = sm + 2 * 128 * ASTR;

    const int ar  = tid >> 3;
    const int af  = (tid & 7) * 4;
    const int bnn = tid & 127;
    const int bkc = tid >> 7;

    const float* Ag = A + (size_t)bm * K;
    const float* Bg = B + bn;

    float4 aS[4], bS[4];

    #pragma unroll
    for (int i = 0; i < 4; i++)
        aS[i] = *(const float4*)(Ag + (size_t)(ar + 32 * i) * K + af);
    #pragma unroll
    for (int i = 0; i < 4; i++) {
        int kb = (bkc + 2 * i) * 4;
        float4 v;
        v.x = Bg[(size_t)(kb + 0) * N + bnn];
        v.y = Bg[(size_t)(kb + 1) * N + bnn];
        v.z = Bg[(size_t)(kb + 2) * N + bnn];
        v.w = Bg[(size_t)(kb + 3) * N + bnn];
        bS[i] = v;
    }

    {
        #pragma unroll
        for (int i = 0; i < 4; i++) {
            float4 cv = make_float4(f2tf(aS[i].x), f2tf(aS[i].y), f2tf(aS[i].z), f2tf(aS[i].w));
            *(float4*)(As + (ar + 32 * i) * ASTR + af) = cv;
        }
        #pragma unroll
        for (int i = 0; i < 4; i++) {
            float4 cv = make_float4(f2tf(bS[i].x), f2tf(bS[i].y), f2tf(bS[i].z), f2tf(bS[i].w));
            *(float4*)(Bs + bnn * ASTR + (bkc + 2 * i) * 4) = cv;
        }
    }
    __syncthreads();

    float c[4][4][4] = {};

    const int nT = K / 32;
    for (int kt = 0; kt < nT; kt++) {
        const int cur = kt & 1;

        if (kt + 1 < nT) {
            const float* Ak = Ag + (kt + 1) * 32;
            #pragma unroll
            for (int i = 0; i < 4; i++)
                aS[i] = *(const float4*)(Ak + (size_t)(ar + 32 * i) * K + af);
            const float* Bk = Bg + (size_t)(kt + 1) * 32 * N;
            #pragma unroll
            for (int i = 0; i < 4; i++) {
                int kb = (bkc + 2 * i) * 4;
                float4 v;
                v.x = Bk[(size_t)(kb + 0) * N + bnn];
                v.y = Bk[(size_t)(kb + 1) * N + bnn];
                v.z = Bk[(size_t)(kb + 2) * N + bnn];
                v.w = Bk[(size_t)(kb + 3) * N + bnn];
                bS[i] = v;
            }
        }

        const float* Ab = As + cur * 128 * ASTR;
        const float* Bb = Bs + cur * 128 * ASTR;
        #pragma unroll
        for (int ks = 0; ks < 4; ks++) {
            uint32_t aF[4][4], bF[4][2];
            #pragma unroll
            for (int mt = 0; mt < 4; mt++) {
                int row = warpM * 64 + mt * 16 + ((lane >> 3) & 1) * 8 + (lane & 7);
                int kof = ks * 8 + (lane >> 4) * 4;
                uint32_t addr = (uint32_t)__cvta_generic_to_shared(Ab + row * ASTR + kof);
                asm volatile("ldmatrix.sync.aligned.m8n8.x4.shared.b16 {%0,%1,%2,%3}, [%4];"
                             : "=r"(aF[mt][0]), "=r"(aF[mt][1]), "=r"(aF[mt][2]), "=r"(aF[mt][3])
                             : "r"(addr));
            }
            #pragma unroll
            for (int nt = 0; nt < 4; nt++) {
                int row = warpN * 32 + nt * 8 + (lane & 7);
                int kof = ks * 8 + ((lane >> 3) & 1) * 4;
                uint32_t addr = (uint32_t)__cvta_generic_to_shared(Bb + row * ASTR + kof);
                asm volatile("ldmatrix.sync.aligned.m8n8.x2.shared.b16 {%0,%1}, [%2];"
                             : "=r"(bF[nt][0]), "=r"(bF[nt][1])
                             : "r"(addr));
            }
            #pragma unroll
            for (int mt = 0; mt < 4; mt++)
                #pragma unroll
                for (int nt = 0; nt < 4; nt++) {
                    asm volatile(
                        "mma.sync.aligned.m16n8k8.row.col.f32.tf32.tf32.f32 "
                        "{%0,%1,%2,%3}, {%4,%5,%6,%7}, {%8,%9}, {%0,%1,%2,%3};"
                        : "+f"(c[mt][nt][0]), "+f"(c[mt][nt][1]),
                          "+f"(c[mt][nt][2]), "+f"(c[mt][nt][3])
                        : "r"(aF[mt][0]), "r"(aF[mt][1]), "r"(aF[mt][2]), "r"(aF[mt][3]),
                          "r"(bF[nt][0]), "r"(bF[nt][1]));
                }
        }

        if (kt + 1 < nT) {
            float* Ao = As + (cur ^ 1) * 128 * ASTR;
            float* Bo = Bs + (cur ^ 1) * 128 * ASTR;
            #pragma unroll
            for (int i = 0; i < 4; i++) {
                float4 cv = make_float4(f2tf(aS[i].x), f2tf(aS[i].y), f2tf(aS[i].z), f2tf(aS[i].w));
                *(float4*)(Ao + (ar + 32 * i) * ASTR + af) = cv;
            }
            #pragma unroll
            for (int i = 0; i < 4; i++) {
                float4 cv = make_float4(f2tf(bS[i].x), f2tf(bS[i].y), f2tf(bS[i].z), f2tf(bS[i].w));
                *(float4*)(Bo + bnn * ASTR + (bkc + 2 * i) * 4) = cv;
            }
            __syncthreads();
        }
    }

    #pragma unroll
    for (int mt = 0; mt < 4; mt++) {
        #pragma unroll
        for (int nt = 0; nt < 4; nt++) {
            int row0 = bm + warpM * 64 + mt * 16 + g;
            int col  = bn + warpN * 32 + nt * 8 + tig * 2;
            float b0 = bias[col], b1 = bias[col + 1];
            float2 v0 = make_float2(c[mt][nt][0] + b0, c[mt][nt][1] + b1);
            float2 v1 = make_float2(c[mt][nt][2] + b0, c[mt][nt][3] + b1);
            *(float2*)&C[(size_t)row0 * N + col] = v0;
            *(float2*)&C[(size_t)(row0 + 8) * N + col] = v1;
        }
    }
}

// ---------------------------------------------------------------------------
// Tensor-core attention: block = (window b, head h), 128 threads (4 warps).
// S(64x56) = scale*q @ k^T via mma; +mask +clip(bias), clip, softmax;
// O(64x32) = P @ V via mma. Padded rows/cols are zeros.
// ---------------------------------------------------------------------------
#define SSTR 60   // Sbuf / vT row stride (floats)

__global__ __launch_bounds__(128)
void attn_mma_kernel(const float* __restrict__ qkv, const float* __restrict__ mask,
                     const float* __restrict__ rel_table, const int* __restrict__ rel_index,
                     float* __restrict__ out)
{
    const int b = blockIdx.x;
    const int h = blockIdx.y;
    const int tid  = threadIdx.x;
    const int lane = tid & 31;
    const int w    = tid >> 5;           // warp 0..3 -> m-tile (16 rows)
    const int g    = lane >> 2;
    const int tig  = lane & 3;

    __shared__ float qs[64 * ASTR];      // (i, d) tf32, rows 49..63 zero
    __shared__ float ks[56 * ASTR];      // (j, d) tf32, rows 49..55 zero
    __shared__ float vT[HD * SSTR];      // (d, j) tf32, cols 49..55 zero
    __shared__ float Sb[64 * SSTR];      // scores -> probs

    const float scale = 0.1767766952966369f;

    // zero pads (full clear of q/k/vT is cheap: 6 KB-ish)
    for (int i = tid; i < 64 * ASTR; i += 128) qs[i] = 0.f;
    for (int i = tid; i < 56 * ASTR; i += 128) ks[i] = 0.f;
    for (int i = tid; i < HD * SSTR; i += 128) vT[i] = 0.f;
    __syncthreads();

    // stage q, k (row-major) and v (transposed), tf32-rounded
    for (int idx = tid; idx < NTOK * HD; idx += 128) {
        int i = idx >> 5;            // token
        int d = idx & 31;
        size_t base = (size_t)(b * NTOK + i) * QKV_N + h * HD + d;
        qs[i * ASTR + d] = f2tf(qkv[base] * scale);
        ks[i * ASTR + d] = f2tf(qkv[base + DIM]);
        vT[d * SSTR + i] = f2tf(qkv[base + 2 * DIM]);
    }
    __syncthreads();

    // ---- S = q @ k^T : warp w computes rows [16w,16w+16), 7 n-tiles, 4 k-steps
    float c[7][4] = {};
    #pragma unroll
    for (int ksi = 0; ksi < 4; ksi++) {
        uint32_t aF[4], bF[7][2];
        {
            int row = w * 16 + ((lane >> 3) & 1) * 8 + (lane & 7);
            int kof = ksi * 8 + (lane >> 4) * 4;
            uint32_t addr = (uint32_t)__cvta_generic_to_shared(qs + row * ASTR + kof);
            asm volatile("ldmatrix.sync.aligned.m8n8.x4.shared.b16 {%0,%1,%2,%3}, [%4];"
                         : "=r"(aF[0]), "=r"(aF[1]), "=r"(aF[2]), "=r"(aF[3]) : "r"(addr));
        }
        #pragma unroll
        for (int nt = 0; nt < 7; nt++) {
            int row = nt * 8 + (lane & 7);
            int kof = ksi * 8 + ((lane >> 3) & 1) * 4;
            uint32_t addr = (uint32_t)__cvta_generic_to_shared(ks + row * ASTR + kof);
            asm volatile("ldmatrix.sync.aligned.m8n8.x2.shared.b16 {%0,%1}, [%2];"
                         : "=r"(bF[nt][0]), "=r"(bF[nt][1]) : "r"(addr));
        }
        #pragma unroll
        for (int nt = 0; nt < 7; nt++)
            asm volatile(
                "mma.sync.aligned.m16n8k8.row.col.f32.tf32.tf32.f32 "
                "{%0,%1,%2,%3}, {%4,%5,%6,%7}, {%8,%9}, {%0,%1,%2,%3};"
                : "+f"(c[nt][0]), "+f"(c[nt][1]), "+f"(c[nt][2]), "+f"(c[nt][3])
                : "r"(aF[0]), "r"(aF[1]), "r"(aF[2]), "r"(aF[3]),
                  "r"(bF[nt][0]), "r"(bF[nt][1]));
    }

    // ---- store S + mask + clip(bias), clip(+-10); pads -> 0
    const float* mwin = mask + (size_t)(b & (NW - 1)) * (NTOK * NTOK);
    #pragma unroll
    for (int nt = 0; nt < 7; nt++) {
        #pragma unroll
        for (int v = 0; v < 4; v++) {
            int i = w * 16 + g + (v >= 2 ? 8 : 0);
            int j = nt * 8 + tig * 2 + (v & 1);
            float val = 0.f;
            if (i < NTOK && j < NTOK) {
                int ij = i * NTOK + j;
                float bia = rel_table[rel_index[ij] * NHEAD + h];
                bia = fminf(fmaxf(bia, -5.f), 5.f);
                val = c[nt][v] + mwin[ij] + bia;
                val = fminf(fmaxf(val, -10.f), 10.f);
            }
            Sb[i * SSTR + j] = val;
        }
    }
    __syncthreads();

    // ---- softmax over valid rows (49), warp-per-row, probs stored tf32
    for (int i = w; i < NTOK; i += 4) {
        float* row = Sb + i * SSTR;
        float m = -1e30f;
        for (int j = lane; j < NTOK; j += 32) m = fmaxf(m, row[j]);
        #pragma unroll
        for (int o = 16; o > 0; o >>= 1) m = fmaxf(m, __shfl_xor_sync(0xffffffffu, m, o));
        float sum = 0.f;
        for (int j = lane; j < NTOK; j += 32) {
            float e = __expf(row[j] - m);
            row[j] = e;
            sum += e;
        }
        #pragma unroll
        for (int o = 16; o > 0; o >>= 1) sum += __shfl_xor_sync(0xffffffffu, sum, o);
        float inv = 1.f / sum;
        for (int j = lane; j < NTOK; j += 32) row[j] = f2tf(row[j] * inv);
        // zero the padded cols 49..55 so the P@V mma sees clean zeros
        if (lane >= NTOK && lane < 56) row[lane] = 0.f;
    }
    // rows 49..63: ensure pad cols are zero too (scores there were 0; cols 49..55 written 0 above only for valid rows)
    for (int i = NTOK + w; i < 64; i += 4)
        if (lane >= NTOK && lane < 56) Sb[i * SSTR + lane] = 0.f;
    __syncthreads();

    // ---- O = P @ V : 7 k-steps (j), 4 n-tiles (d)
    float o[4][4] = {};
    #pragma unroll
    for (int ksi = 0; ksi < 7; ksi++) {
        uint32_t aF[4], bF[4][2];
        {
            int row = w * 16 + ((lane >> 3) & 1) * 8 + (lane & 7);
            int kof = ksi * 8 + (lane >> 4) * 4;
            uint32_t addr = (uint32_t)__cvta_generic_to_shared(Sb + row * SSTR + kof);
            asm volatile("ldmatrix.sync.aligned.m8n8.x4.shared.b16 {%0,%1,%2,%3}, [%4];"
                         : "=r"(aF[0]), "=r"(aF[1]), "=r"(aF[2]), "=r"(aF[3]) : "r"(addr));
        }
        #pragma unroll
        for (int nt = 0; nt < 4; nt++) {
            int row = nt * 8 + (lane & 7);          // d index
            int kof = ksi * 8 + ((lane >> 3) & 1) * 4;
            uint32_t addr = (uint32_t)__cvta_generic_to_shared(vT + row * SSTR + kof);
            asm volatile("ldmatrix.sync.aligned.m8n8.x2.shared.b16 {%0,%1}, [%2];"
                         : "=r"(bF[nt][0]), "=r"(bF[nt][1]) : "r"(addr));
        }
        #pragma unroll
        for (int nt = 0; nt < 4; nt++)
            asm volatile(
                "mma.sync.aligned.m16n8k8.row.col.f32.tf32.tf32.f32 "
                "{%0,%1,%2,%3}, {%4,%5,%6,%7}, {%8,%9}, {%0,%1,%2,%3};"
                : "+f"(o[nt][0]), "+f"(o[nt][1]), "+f"(o[nt][2]), "+f"(o[nt][3])
                : "r"(aF[0]), "r"(aF[1]), "r"(aF[2]), "r"(aF[3]),
                  "r"(bF[nt][0]), "r"(bF[nt][1]));
    }

    // ---- store O rows < 49
    #pragma unroll
    for (int nt = 0; nt < 4; nt++) {
        int col = nt * 8 + tig * 2;
        int i0 = w * 16 + g;
        if (i0 < NTOK)
            *(float2*)&out[(size_t)(b * NTOK + i0) * DIM + h * HD + col] =
                make_float2(o[nt][0], o[nt][1]);
        int i1 = i0 + 8;
        if (i1 < NTOK)
            *(float2*)&out[(size_t)(b * NTOK + i1) * DIM + h * HD + col] =
                make_float2(o[nt][2], o[nt][3]);
    }
}

// ---------------------------------------------------------------------------
// Launch
// ---------------------------------------------------------------------------
extern "C" void kernel_launch(void* const* d_in, const int* in_sizes, int n_in,
                              void* d_out, int out_size)
{
    const float* x = nullptr;
    const float* mask = nullptr;
    const float* qkv_w = nullptr;
    const float* qkv_b = nullptr;
    const float* proj_w = nullptr;
    const float* proj_b = nullptr;
    const float* rel_table = nullptr;
    const int*   rel_index = nullptr;

    for (int i = 0; i < n_in; i++) {
        switch (in_sizes[i]) {
            case 77070336: x         = (const float*)d_in[i]; break;
            case 614656:   mask      = (const float*)d_in[i]; break;
            case 442368:   qkv_w     = (const float*)d_in[i]; break;
            case 1152:     qkv_b     = (const float*)d_in[i]; break;
            case 147456:   proj_w    = (const float*)d_in[i]; break;
            case 384:      proj_b    = (const float*)d_in[i]; break;
            case 2028:     rel_table = (const float*)d_in[i]; break;
            case 2401:     rel_index = (const int*)d_in[i];   break;
            default: break;
        }
    }

    float* qkv_s = nullptr;
    float* att_s = nullptr;
    cudaGetSymbolAddress((void**)&qkv_s, g_qkv);
    cudaGetSymbolAddress((void**)&att_s, g_att);

    cudaFuncSetAttribute(tf32_gemm_bias, cudaFuncAttributeMaxDynamicSharedMemorySize, SMEM_BYTES);

    // 1) QKV GEMM
    dim3 g1(QKV_N / 128, M_ROWS / 128);
    tf32_gemm_bias<<<g1, 256, SMEM_BYTES>>>(x, qkv_w, qkv_b, qkv_s, M_ROWS, QKV_N, DIM);

    // 2) Tensor-core attention
    dim3 g2(BW, NHEAD);
    attn_mma_kernel<<<g2, 128>>>(qkv_s, mask, rel_table, rel_index, att_s);

    // 3) Proj GEMM -> d_out
    dim3 g3(DIM / 128, M_ROWS / 128);
    tf32_gemm_bias<<<g3, 256, SMEM_BYTES>>>(att_s, proj_w, proj_b, (float*)d_out, M_ROWS, DIM, DIM);
}

// round 10
// speedup vs baseline: 1.6475x; 1.6475x over previous
#include <cuda_runtime.h>
#include <cuda_bf16.h>
#include <math.h>
#include <stdint.h>

// ---------------------------------------------------------------------------
// WindowAttention: tf32 tensor-core GEMMs + fused-softmax tensor-core attention
// ---------------------------------------------------------------------------

#define BW      4096
#define NTOK    49
#define DIM     384
#define NHEAD   12
#define HD      32
#define NW      256
#define M_ROWS  (BW * NTOK)        // 200704
#define QKV_N   (3 * DIM)          // 1152

__device__ float g_qkv[(size_t)M_ROWS * QKV_N];   // ~925 MB
__device__ float g_att[(size_t)M_ROWS * DIM];     // ~308 MB

__device__ __forceinline__ float f2tf(float x) {
    uint32_t r;
    asm("cvt.rna.tf32.f32 %0, %1;" : "=r"(r) : "f"(x));
    return __uint_as_float(r);
}

// ---------------------------------------------------------------------------
// tf32 tensor-core GEMM (exact R5 config — known good, no reg cap / no spills)
// C[M,N] = A[M,K] @ B[K,N] + bias[N]; 128x128x32 tile, 256 thr, warp 64x32.
// ---------------------------------------------------------------------------
#define ASTR 36
#define SMEM_BYTES (2 * 128 * ASTR * 4 * 2)   // 73728

__global__ __launch_bounds__(256)
void tf32_gemm_bias(const float* __restrict__ A, const float* __restrict__ B,
                    const float* __restrict__ bias, float* __restrict__ C,
                    int M, int N, int K)
{
    const int tid  = threadIdx.x;
    const int lane = tid & 31;
    const int wid  = tid >> 5;
    const int warpM = wid & 1;
    const int warpN = wid >> 1;
    const int g   = lane >> 2;
    const int tig = lane & 3;

    const int bn = blockIdx.x * 128;
    const int bm = blockIdx.y * 128;

    extern __shared__ float sm[];
    float* As = sm;
    float* Bs = sm + 2 * 128 * ASTR;

    const int ar  = tid >> 3;
    const int af  = (tid & 7) * 4;
    const int bnn = tid & 127;
    const int bkc = tid >> 7;

    const float* Ag = A + (size_t)bm * K;
    const float* Bg = B + bn;

    float4 aS[4], bS[4];

    #pragma unroll
    for (int i = 0; i < 4; i++)
        aS[i] = *(const float4*)(Ag + (size_t)(ar + 32 * i) * K + af);
    #pragma unroll
    for (int i = 0; i < 4; i++) {
        int kb = (bkc + 2 * i) * 4;
        float4 v;
        v.x = Bg[(size_t)(kb + 0) * N + bnn];
        v.y = Bg[(size_t)(kb + 1) * N + bnn];
        v.z = Bg[(size_t)(kb + 2) * N + bnn];
        v.w = Bg[(size_t)(kb + 3) * N + bnn];
        bS[i] = v;
    }

    {
        #pragma unroll
        for (int i = 0; i < 4; i++) {
            float4 cv = make_float4(f2tf(aS[i].x), f2tf(aS[i].y), f2tf(aS[i].z), f2tf(aS[i].w));
            *(float4*)(As + (ar + 32 * i) * ASTR + af) = cv;
        }
        #pragma unroll
        for (int i = 0; i < 4; i++) {
            float4 cv = make_float4(f2tf(bS[i].x), f2tf(bS[i].y), f2tf(bS[i].z), f2tf(bS[i].w));
            *(float4*)(Bs + bnn * ASTR + (bkc + 2 * i) * 4) = cv;
        }
    }
    __syncthreads();

    float c[4][4][4] = {};

    const int nT = K / 32;
    for (int kt = 0; kt < nT; kt++) {
        const int cur = kt & 1;

        if (kt + 1 < nT) {
            const float* Ak = Ag + (kt + 1) * 32;
            #pragma unroll
            for (int i = 0; i < 4; i++)
                aS[i] = *(const float4*)(Ak + (size_t)(ar + 32 * i) * K + af);
            const float* Bk = Bg + (size_t)(kt + 1) * 32 * N;
            #pragma unroll
            for (int i = 0; i < 4; i++) {
                int kb = (bkc + 2 * i) * 4;
                float4 v;
                v.x = Bk[(size_t)(kb + 0) * N + bnn];
                v.y = Bk[(size_t)(kb + 1) * N + bnn];
                v.z = Bk[(size_t)(kb + 2) * N + bnn];
                v.w = Bk[(size_t)(kb + 3) * N + bnn];
                bS[i] = v;
            }
        }

        const float* Ab = As + cur * 128 * ASTR;
        const float* Bb = Bs + cur * 128 * ASTR;
        #pragma unroll
        for (int ks = 0; ks < 4; ks++) {
            uint32_t aF[4][4], bF[4][2];
            #pragma unroll
            for (int mt = 0; mt < 4; mt++) {
                int row = warpM * 64 + mt * 16 + ((lane >> 3) & 1) * 8 + (lane & 7);
                int kof = ks * 8 + (lane >> 4) * 4;
                uint32_t addr = (uint32_t)__cvta_generic_to_shared(Ab + row * ASTR + kof);
                asm volatile("ldmatrix.sync.aligned.m8n8.x4.shared.b16 {%0,%1,%2,%3}, [%4];"
                             : "=r"(aF[mt][0]), "=r"(aF[mt][1]), "=r"(aF[mt][2]), "=r"(aF[mt][3])
                             : "r"(addr));
            }
            #pragma unroll
            for (int nt = 0; nt < 4; nt++) {
                int row = warpN * 32 + nt * 8 + (lane & 7);
                int kof = ks * 8 + ((lane >> 3) & 1) * 4;
                uint32_t addr = (uint32_t)__cvta_generic_to_shared(Bb + row * ASTR + kof);
                asm volatile("ldmatrix.sync.aligned.m8n8.x2.shared.b16 {%0,%1}, [%2];"
                             : "=r"(bF[nt][0]), "=r"(bF[nt][1])
                             : "r"(addr));
            }
            #pragma unroll
            for (int mt = 0; mt < 4; mt++)
                #pragma unroll
                for (int nt = 0; nt < 4; nt++) {
                    asm volatile(
                        "mma.sync.aligned.m16n8k8.row.col.f32.tf32.tf32.f32 "
                        "{%0,%1,%2,%3}, {%4,%5,%6,%7}, {%8,%9}, {%0,%1,%2,%3};"
                        : "+f"(c[mt][nt][0]), "+f"(c[mt][nt][1]),
                          "+f"(c[mt][nt][2]), "+f"(c[mt][nt][3])
                        : "r"(aF[mt][0]), "r"(aF[mt][1]), "r"(aF[mt][2]), "r"(aF[mt][3]),
                          "r"(bF[nt][0]), "r"(bF[nt][1]));
                }
        }

        if (kt + 1 < nT) {
            float* Ao = As + (cur ^ 1) * 128 * ASTR;
            float* Bo = Bs + (cur ^ 1) * 128 * ASTR;
            #pragma unroll
            for (int i = 0; i < 4; i++) {
                float4 cv = make_float4(f2tf(aS[i].x), f2tf(aS[i].y), f2tf(aS[i].z), f2tf(aS[i].w));
                *(float4*)(Ao + (ar + 32 * i) * ASTR + af) = cv;
            }
            #pragma unroll
            for (int i = 0; i < 4; i++) {
                float4 cv = make_float4(f2tf(bS[i].x), f2tf(bS[i].y), f2tf(bS[i].z), f2tf(bS[i].w));
                *(float4*)(Bo + bnn * ASTR + (bkc + 2 * i) * 4) = cv;
            }
            __syncthreads();
        }
    }

    #pragma unroll
    for (int mt = 0; mt < 4; mt++) {
        #pragma unroll
        for (int nt = 0; nt < 4; nt++) {
            int row0 = bm + warpM * 64 + mt * 16 + g;
            int col  = bn + warpN * 32 + nt * 8 + tig * 2;
            float b0 = bias[col], b1 = bias[col + 1];
            float2 v0 = make_float2(c[mt][nt][0] + b0, c[mt][nt][1] + b1);
            float2 v1 = make_float2(c[mt][nt][2] + b0, c[mt][nt][3] + b1);
            *(float2*)&C[(size_t)row0 * N + col] = v0;
            *(float2*)&C[(size_t)(row0 + 8) * N + col] = v1;
        }
    }
}

// ---------------------------------------------------------------------------
// Fused-softmax tensor-core attention. Block = (window b, head h), 128 thr.
// Scores clipped to [-10,10] => exp never overflows => NO max pass.
// e=exp(s) fused into S-epilogue; row sums via quad shuffles; normalization
// deferred to O store. Sb aliases qs/ks (dead after S-mma): 25KB smem.
// 3 __syncthreads total.
// ---------------------------------------------------------------------------
#define SSTR 60

__global__ __launch_bounds__(128, 6)
void attn_mma_kernel(const float* __restrict__ qkv, const float* __restrict__ mask,
                     const float* __restrict__ rel_table, const int* __restrict__ rel_index,
                     float* __restrict__ out)
{
    const int b = blockIdx.x;
    const int h = blockIdx.y;
    const int tid  = threadIdx.x;
    const int lane = tid & 31;
    const int w    = tid >> 5;
    const int g    = lane >> 2;
    const int tig  = lane & 3;

    __shared__ float u[64 * ASTR + 56 * ASTR];   // qs(64xASTR)+ks(56xASTR); later Sb(64xSSTR)
    __shared__ float vT[HD * SSTR];
    __shared__ float rowsum[64];

    float* qs = u;
    float* ks = u + 64 * ASTR;
    float* Sb = u;

    const float scale = 0.1767766952966369f;

    // ---- precise pad zeroing (disjoint from staged region -> no extra sync)
    for (int idx = tid; idx < 15 * 32; idx += 128) {           // qs rows 49..63
        int r = 49 + (idx >> 5);
        qs[r * ASTR + (idx & 31)] = 0.f;
    }
    for (int idx = tid; idx < 7 * 32; idx += 128) {            // ks rows 49..55
        int r = 49 + (idx >> 5);
        ks[r * ASTR + (idx & 31)] = 0.f;
    }
    for (int idx = tid; idx < 32 * 7; idx += 128) {            // vT cols 49..55
        int d = idx / 7;
        vT[d * SSTR + 49 + (idx % 7)] = 0.f;
    }

    // ---- stage q (scaled), k row-major; v transposed; all tf32 (float4 loads)
    for (int idx = tid; idx < NTOK * 8; idx += 128) {
        int i  = idx >> 3;
        int qd = (idx & 7) * 4;
        const float* base = qkv + (size_t)(b * NTOK + i) * QKV_N + h * HD + qd;
        float4 qv = *(const float4*)(base);
        float4 kv = *(const float4*)(base + DIM);
        float4 vv = *(const float4*)(base + 2 * DIM);
        *(float4*)(qs + i * ASTR + qd) =
            make_float4(f2tf(qv.x * scale), f2tf(qv.y * scale), f2tf(qv.z * scale), f2tf(qv.w * scale));
        *(float4*)(ks + i * ASTR + qd) =
            make_float4(f2tf(kv.x), f2tf(kv.y), f2tf(kv.z), f2tf(kv.w));
        vT[(qd + 0) * SSTR + i] = f2tf(vv.x);
        vT[(qd + 1) * SSTR + i] = f2tf(vv.y);
        vT[(qd + 2) * SSTR + i] = f2tf(vv.z);
        vT[(qd + 3) * SSTR + i] = f2tf(vv.w);
    }
    __syncthreads();   // (1)

    // ---- S = q @ k^T : warp w -> rows [16w,16w+16), 7 n-tiles, 4 k-steps
    float c[7][4] = {};
    #pragma unroll
    for (int ksi = 0; ksi < 4; ksi++) {
        uint32_t aF[4], bF[7][2];
        {
            int row = w * 16 + ((lane >> 3) & 1) * 8 + (lane & 7);
            int kof = ksi * 8 + (lane >> 4) * 4;
            uint32_t addr = (uint32_t)__cvta_generic_to_shared(qs + row * ASTR + kof);
            asm volatile("ldmatrix.sync.aligned.m8n8.x4.shared.b16 {%0,%1,%2,%3}, [%4];"
                         : "=r"(aF[0]), "=r"(aF[1]), "=r"(aF[2]), "=r"(aF[3]) : "r"(addr));
        }
        #pragma unroll
        for (int nt = 0; nt < 7; nt++) {
            int row = nt * 8 + (lane & 7);
            int kof = ksi * 8 + ((lane >> 3) & 1) * 4;
            uint32_t addr = (uint32_t)__cvta_generic_to_shared(ks + row * ASTR + kof);
            asm volatile("ldmatrix.sync.aligned.m8n8.x2.shared.b16 {%0,%1}, [%2];"
                         : "=r"(bF[nt][0]), "=r"(bF[nt][1]) : "r"(addr));
        }
        #pragma unroll
        for (int nt = 0; nt < 7; nt++)
            asm volatile(
                "mma.sync.aligned.m16n8k8.row.col.f32.tf32.tf32.f32 "
                "{%0,%1,%2,%3}, {%4,%5,%6,%7}, {%8,%9}, {%0,%1,%2,%3};"
                : "+f"(c[nt][0]), "+f"(c[nt][1]), "+f"(c[nt][2]), "+f"(c[nt][3])
                : "r"(aF[0]), "r"(aF[1]), "r"(aF[2]), "r"(aF[3]),
                  "r"(bF[nt][0]), "r"(bF[nt][1]));
    }

    // ---- fused epilogue: +mask +clip(bias), clip(+-10), exp, partial row sums
    const float* mwin = mask + (size_t)(b & (NW - 1)) * (NTOK * NTOK);
    const int i0 = w * 16 + g;
    const int i1 = i0 + 8;
    float p0 = 0.f, p1 = 0.f;
    #pragma unroll
    for (int nt = 0; nt < 7; nt++) {
        #pragma unroll
        for (int v = 0; v < 4; v++) {
            int i = (v >= 2) ? i1 : i0;
            int j = nt * 8 + tig * 2 + (v & 1);
            float ev = 0.f;
            if (i < NTOK && j < NTOK) {
                int ij = i * NTOK + j;
                float bia = rel_table[rel_index[ij] * NHEAD + h];
                bia = fminf(fmaxf(bia, -5.f), 5.f);
                float val = c[nt][v] + mwin[ij] + bia;
                val = fminf(fmaxf(val, -10.f), 10.f);
                ev = __expf(val);
            }
            c[nt][v] = ev;
            if (v < 2) p0 += ev; else p1 += ev;
        }
    }
    // quad reduction (lanes g*4..g*4+3 share rows i0/i1)
    p0 += __shfl_xor_sync(0xffffffffu, p0, 1);
    p0 += __shfl_xor_sync(0xffffffffu, p0, 2);
    p1 += __shfl_xor_sync(0xffffffffu, p1, 1);
    p1 += __shfl_xor_sync(0xffffffffu, p1, 2);

    __syncthreads();   // (2) qs/ks dead -> safe to overwrite with Sb

    #pragma unroll
    for (int nt = 0; nt < 7; nt++) {
        #pragma unroll
        for (int v = 0; v < 4; v++) {
            int i = (v >= 2) ? i1 : i0;
            int j = nt * 8 + tig * 2 + (v & 1);
            Sb[i * SSTR + j] = f2tf(c[nt][v]);
        }
    }
    if (tig == 0) {
        rowsum[i0] = p0;
        rowsum[i1] = p1;
    }
    __syncthreads();   // (3)

    // ---- O = P @ V : 7 k-steps, 4 n-tiles (d)
    float o[4][4] = {};
    #pragma unroll
    for (int ksi = 0; ksi < 7; ksi++) {
        uint32_t aF[4], bF[4][2];
        {
            int row = w * 16 + ((lane >> 3) & 1) * 8 + (lane & 7);
            int kof = ksi * 8 + (lane >> 4) * 4;
            uint32_t addr = (uint32_t)__cvta_generic_to_shared(Sb + row * SSTR + kof);
            asm volatile("ldmatrix.sync.aligned.m8n8.x4.shared.b16 {%0,%1,%2,%3}, [%4];"
                         : "=r"(aF[0]), "=r"(aF[1]), "=r"(aF[2]), "=r"(aF[3]) : "r"(addr));
        }
        #pragma unroll
        for (int nt = 0; nt < 4; nt++) {
            int row = nt * 8 + (lane & 7);
            int kof = ksi * 8 + ((lane >> 3) & 1) * 4;
            uint32_t addr = (uint32_t)__cvta_generic_to_shared(vT + row * SSTR + kof);
            asm volatile("ldmatrix.sync.aligned.m8n8.x2.shared.b16 {%0,%1}, [%2];"
                         : "=r"(bF[nt][0]), "=r"(bF[nt][1]) : "r"(addr));
        }
        #pragma unroll
        for (int nt = 0; nt < 4; nt++)
            asm volatile(
                "mma.sync.aligned.m16n8k8.row.col.f32.tf32.tf32.f32 "
                "{%0,%1,%2,%3}, {%4,%5,%6,%7}, {%8,%9}, {%0,%1,%2,%3};"
                : "+f"(o[nt][0]), "+f"(o[nt][1]), "+f"(o[nt][2]), "+f"(o[nt][3])
                : "r"(aF[0]), "r"(aF[1]), "r"(aF[2]), "r"(aF[3]),
                  "r"(bF[nt][0]), "r"(bF[nt][1]));
    }

    // ---- normalize at store
    float inv0 = 1.f / rowsum[i0];
    float inv1 = 1.f / rowsum[i1];
    #pragma unroll
    for (int nt = 0; nt < 4; nt++) {
        int col = nt * 8 + tig * 2;
        if (i0 < NTOK)
            *(float2*)&out[(size_t)(b * NTOK + i0) * DIM + h * HD + col] =
                make_float2(o[nt][0] * inv0, o[nt][1] * inv0);
        if (i1 < NTOK)
            *(float2*)&out[(size_t)(b * NTOK + i1) * DIM + h * HD + col] =
                make_float2(o[nt][2] * inv1, o[nt][3] * inv1);
    }
}

// ---------------------------------------------------------------------------
// Launch
// ---------------------------------------------------------------------------
extern "C" void kernel_launch(void* const* d_in, const int* in_sizes, int n_in,
                              void* d_out, int out_size)
{
    const float* x = nullptr;
    const float* mask = nullptr;
    const float* qkv_w = nullptr;
    const float* qkv_b = nullptr;
    const float* proj_w = nullptr;
    const float* proj_b = nullptr;
    const float* rel_table = nullptr;
    const int*   rel_index = nullptr;

    for (int i = 0; i < n_in; i++) {
        switch (in_sizes[i]) {
            case 77070336: x         = (const float*)d_in[i]; break;
            case 614656:   mask      = (const float*)d_in[i]; break;
            case 442368:   qkv_w     = (const float*)d_in[i]; break;
            case 1152:     qkv_b     = (const float*)d_in[i]; break;
            case 147456:   proj_w    = (const float*)d_in[i]; break;
            case 384:      proj_b    = (const float*)d_in[i]; break;
            case 2028:     rel_table = (const float*)d_in[i]; break;
            case 2401:     rel_index = (const int*)d_in[i];   break;
            default: break;
        }
    }

    float* qkv_s = nullptr;
    float* att_s = nullptr;
    cudaGetSymbolAddress((void**)&qkv_s, g_qkv);
    cudaGetSymbolAddress((void**)&att_s, g_att);

    cudaFuncSetAttribute(tf32_gemm_bias, cudaFuncAttributeMaxDynamicSharedMemorySize, SMEM_BYTES);

    // 1) QKV GEMM
    dim3 g1(QKV_N / 128, M_ROWS / 128);
    tf32_gemm_bias<<<g1, 256, SMEM_BYTES>>>(x, qkv_w, qkv_b, qkv_s, M_ROWS, QKV_N, DIM);

    // 2) Fused-softmax tensor-core attention
    dim3 g2(BW, NHEAD);
    attn_mma_kernel<<<g2, 128>>>(qkv_s, mask, rel_table, rel_index, att_s);

    // 3) Proj GEMM -> d_out
    dim3 g3(DIM / 128, M_ROWS / 128);
    tf32_gemm_bias<<<g3, 256, SMEM_BYTES>>>(att_s, proj_w, proj_b, (float*)d_out, M_ROWS, DIM, DIM);
}

// round 11
// speedup vs baseline: 1.9532x; 1.1856x over previous
#include <cuda_runtime.h>
#include <cuda_bf16.h>
#include <math.h>
#include <stdint.h>

// ---------------------------------------------------------------------------
// WindowAttention: cp.async tf32 GEMMs (pre-transposed B) + fused attention
// ---------------------------------------------------------------------------

#define BW      4096
#define NTOK    49
#define DIM     384
#define NHEAD   12
#define HD      32
#define NW      256
#define M_ROWS  (BW * NTOK)        // 200704
#define QKV_N   (3 * DIM)          // 1152

__device__ float g_qkv[(size_t)M_ROWS * QKV_N];   // ~925 MB
__device__ float g_att[(size_t)M_ROWS * DIM];     // ~308 MB
__device__ float g_qkvwT[QKV_N * DIM];            // qkv_w^T  [1152,384]
__device__ float g_projwT[DIM * DIM];             // proj_w^T [384,384]

__device__ __forceinline__ float f2tf(float x) {
    uint32_t r;
    asm("cvt.rna.tf32.f32 %0, %1;" : "=r"(r) : "f"(x));
    return __uint_as_float(r);
}
__device__ __forceinline__ uint32_t u2tf(uint32_t x) {
    uint32_t r;
    asm("cvt.rna.tf32.f32 %0, %1;" : "=r"(r) : "f"(__uint_as_float(x)));
    return r;
}

// ---------------------------------------------------------------------------
// Weight transpose: out[N][K] = in[K][N]. K,N multiples of 32.
// ---------------------------------------------------------------------------
__global__ void transpose_kernel(const float* __restrict__ in, float* __restrict__ out,
                                 int K, int N)
{
    __shared__ float t[32][33];
    int n0 = blockIdx.x * 32, k0 = blockIdx.y * 32;
    t[threadIdx.y][threadIdx.x] = in[(size_t)(k0 + threadIdx.y) * N + n0 + threadIdx.x];
    __syncthreads();
    out[(size_t)(n0 + threadIdx.y) * K + k0 + threadIdx.x] = t[threadIdx.x][threadIdx.y];
}

// ---------------------------------------------------------------------------
// tf32 GEMM v2: C[M,N] = A[M,K] @ Bt[N,K]^T + bias[N]
// 128x128x32 tile, 256 thr, warp 64x32, 3-stage cp.async pipeline.
// tf32 rounding applied to fragments after ldmatrix.
// ---------------------------------------------------------------------------
#define ASTR 36
#define STAGES 3
#define STAGE_FLOATS (2 * 128 * ASTR)                 // A + B per stage
#define SMEM_BYTES_V2 (STAGES * STAGE_FLOATS * 4)     // 110592

__global__ __launch_bounds__(256, 2)
void tf32_gemm_v2(const float* __restrict__ A, const float* __restrict__ Bt,
                  const float* __restrict__ bias, float* __restrict__ C,
                  int M, int N, int K)
{
    const int tid  = threadIdx.x;
    const int lane = tid & 31;
    const int wid  = tid >> 5;
    const int warpM = wid & 1;
    const int warpN = wid >> 1;
    const int g   = lane >> 2;
    const int tig = lane & 3;

    const int bn = blockIdx.x * 128;
    const int bm = blockIdx.y * 128;

    extern __shared__ float sm[];

    const float* Agb = A  + (size_t)bm * K;
    const float* Bgb = Bt + (size_t)bn * K;

    // cp.async one tile (A+B) into stage s: 2*1024 chunks of 16B, 8 per thread
    auto issue_tile = [&](int kt, int s) {
        const float* Ag = Agb + kt * 32;
        const float* Bg = Bgb + kt * 32;
        float* As = sm + s * STAGE_FLOATS;
        float* Bs = As + 128 * ASTR;
        #pragma unroll
        for (int i = 0; i < 4; i++) {
            int c   = tid + 256 * i;
            int row = c >> 3;
            int kof = (c & 7) * 4;
            uint32_t sa = (uint32_t)__cvta_generic_to_shared(As + row * ASTR + kof);
            asm volatile("cp.async.cg.shared.global [%0], [%1], 16;"
                         :: "r"(sa), "l"(Ag + (size_t)row * K + kof));
            uint32_t sb = (uint32_t)__cvta_generic_to_shared(Bs + row * ASTR + kof);
            asm volatile("cp.async.cg.shared.global [%0], [%1], 16;"
                         :: "r"(sb), "l"(Bg + (size_t)row * K + kof));
        }
        asm volatile("cp.async.commit_group;");
    };

    const int nT = K / 32;     // 12

    issue_tile(0, 0);
    if (nT > 1) issue_tile(1, 1);

    float c[4][4][4] = {};

    for (int kt = 0; kt < nT; kt++) {
        if (kt + 1 < nT) asm volatile("cp.async.wait_group 1;");
        else             asm volatile("cp.async.wait_group 0;");
        __syncthreads();

        if (kt + 2 < nT) issue_tile(kt + 2, (kt + 2) % STAGES);

        const float* Ab = sm + (kt % STAGES) * STAGE_FLOATS;
        const float* Bb = Ab + 128 * ASTR;

        #pragma unroll
        for (int ks = 0; ks < 4; ks++) {
            uint32_t aF[4][4], bF[4][2];
            #pragma unroll
            for (int mt = 0; mt < 4; mt++) {
                int row = warpM * 64 + mt * 16 + ((lane >> 3) & 1) * 8 + (lane & 7);
                int kof = ks * 8 + (lane >> 4) * 4;
                uint32_t addr = (uint32_t)__cvta_generic_to_shared(Ab + row * ASTR + kof);
                asm volatile("ldmatrix.sync.aligned.m8n8.x4.shared.b16 {%0,%1,%2,%3}, [%4];"
                             : "=r"(aF[mt][0]), "=r"(aF[mt][1]), "=r"(aF[mt][2]), "=r"(aF[mt][3])
                             : "r"(addr));
                aF[mt][0] = u2tf(aF[mt][0]); aF[mt][1] = u2tf(aF[mt][1]);
                aF[mt][2] = u2tf(aF[mt][2]); aF[mt][3] = u2tf(aF[mt][3]);
            }
            #pragma unroll
            for (int nt = 0; nt < 4; nt++) {
                int row = warpN * 32 + nt * 8 + (lane & 7);
                int kof = ks * 8 + ((lane >> 3) & 1) * 4;
                uint32_t addr = (uint32_t)__cvta_generic_to_shared(Bb + row * ASTR + kof);
                asm volatile("ldmatrix.sync.aligned.m8n8.x2.shared.b16 {%0,%1}, [%2];"
                             : "=r"(bF[nt][0]), "=r"(bF[nt][1])
                             : "r"(addr));
                bF[nt][0] = u2tf(bF[nt][0]); bF[nt][1] = u2tf(bF[nt][1]);
            }
            #pragma unroll
            for (int mt = 0; mt < 4; mt++)
                #pragma unroll
                for (int nt = 0; nt < 4; nt++) {
                    asm volatile(
                        "mma.sync.aligned.m16n8k8.row.col.f32.tf32.tf32.f32 "
                        "{%0,%1,%2,%3}, {%4,%5,%6,%7}, {%8,%9}, {%0,%1,%2,%3};"
                        : "+f"(c[mt][nt][0]), "+f"(c[mt][nt][1]),
                          "+f"(c[mt][nt][2]), "+f"(c[mt][nt][3])
                        : "r"(aF[mt][0]), "r"(aF[mt][1]), "r"(aF[mt][2]), "r"(aF[mt][3]),
                          "r"(bF[nt][0]), "r"(bF[nt][1]));
                }
        }
        __syncthreads();
    }

    #pragma unroll
    for (int mt = 0; mt < 4; mt++) {
        #pragma unroll
        for (int nt = 0; nt < 4; nt++) {
            int row0 = bm + warpM * 64 + mt * 16 + g;
            int col  = bn + warpN * 32 + nt * 8 + tig * 2;
            float b0 = bias[col], b1 = bias[col + 1];
            float2 v0 = make_float2(c[mt][nt][0] + b0, c[mt][nt][1] + b1);
            float2 v1 = make_float2(c[mt][nt][2] + b0, c[mt][nt][3] + b1);
            *(float2*)&C[(size_t)row0 * N + col] = v0;
            *(float2*)&C[(size_t)(row0 + 8) * N + col] = v1;
        }
    }
}

// ---------------------------------------------------------------------------
// Fused-softmax tensor-core attention (unchanged from R10 — known good).
// ---------------------------------------------------------------------------
#define SSTR 60

__global__ __launch_bounds__(128, 6)
void attn_mma_kernel(const float* __restrict__ qkv, const float* __restrict__ mask,
                     const float* __restrict__ rel_table, const int* __restrict__ rel_index,
                     float* __restrict__ out)
{
    const int b = blockIdx.x;
    const int h = blockIdx.y;
    const int tid  = threadIdx.x;
    const int lane = tid & 31;
    const int w    = tid >> 5;
    const int g    = lane >> 2;
    const int tig  = lane & 3;

    __shared__ float u[64 * ASTR + 56 * ASTR];
    __shared__ float vT[HD * SSTR];
    __shared__ float rowsum[64];

    float* qs = u;
    float* ks = u + 64 * ASTR;
    float* Sb = u;

    const float scale = 0.1767766952966369f;

    for (int idx = tid; idx < 15 * 32; idx += 128) {
        int r = 49 + (idx >> 5);
        qs[r * ASTR + (idx & 31)] = 0.f;
    }
    for (int idx = tid; idx < 7 * 32; idx += 128) {
        int r = 49 + (idx >> 5);
        ks[r * ASTR + (idx & 31)] = 0.f;
    }
    for (int idx = tid; idx < 32 * 7; idx += 128) {
        int d = idx / 7;
        vT[d * SSTR + 49 + (idx % 7)] = 0.f;
    }

    for (int idx = tid; idx < NTOK * 8; idx += 128) {
        int i  = idx >> 3;
        int qd = (idx & 7) * 4;
        const float* base = qkv + (size_t)(b * NTOK + i) * QKV_N + h * HD + qd;
        float4 qv = *(const float4*)(base);
        float4 kv = *(const float4*)(base + DIM);
        float4 vv = *(const float4*)(base + 2 * DIM);
        *(float4*)(qs + i * ASTR + qd) =
            make_float4(f2tf(qv.x * scale), f2tf(qv.y * scale), f2tf(qv.z * scale), f2tf(qv.w * scale));
        *(float4*)(ks + i * ASTR + qd) =
            make_float4(f2tf(kv.x), f2tf(kv.y), f2tf(kv.z), f2tf(kv.w));
        vT[(qd + 0) * SSTR + i] = f2tf(vv.x);
        vT[(qd + 1) * SSTR + i] = f2tf(vv.y);
        vT[(qd + 2) * SSTR + i] = f2tf(vv.z);
        vT[(qd + 3) * SSTR + i] = f2tf(vv.w);
    }
    __syncthreads();

    float c[7][4] = {};
    #pragma unroll
    for (int ksi = 0; ksi < 4; ksi++) {
        uint32_t aF[4], bF[7][2];
        {
            int row = w * 16 + ((lane >> 3) & 1) * 8 + (lane & 7);
            int kof = ksi * 8 + (lane >> 4) * 4;
            uint32_t addr = (uint32_t)__cvta_generic_to_shared(qs + row * ASTR + kof);
            asm volatile("ldmatrix.sync.aligned.m8n8.x4.shared.b16 {%0,%1,%2,%3}, [%4];"
                         : "=r"(aF[0]), "=r"(aF[1]), "=r"(aF[2]), "=r"(aF[3]) : "r"(addr));
        }
        #pragma unroll
        for (int nt = 0; nt < 7; nt++) {
            int row = nt * 8 + (lane & 7);
            int kof = ksi * 8 + ((lane >> 3) & 1) * 4;
            uint32_t addr = (uint32_t)__cvta_generic_to_shared(ks + row * ASTR + kof);
            asm volatile("ldmatrix.sync.aligned.m8n8.x2.shared.b16 {%0,%1}, [%2];"
                         : "=r"(bF[nt][0]), "=r"(bF[nt][1]) : "r"(addr));
        }
        #pragma unroll
        for (int nt = 0; nt < 7; nt++)
            asm volatile(
                "mma.sync.aligned.m16n8k8.row.col.f32.tf32.tf32.f32 "
                "{%0,%1,%2,%3}, {%4,%5,%6,%7}, {%8,%9}, {%0,%1,%2,%3};"
                : "+f"(c[nt][0]), "+f"(c[nt][1]), "+f"(c[nt][2]), "+f"(c[nt][3])
                : "r"(aF[0]), "r"(aF[1]), "r"(aF[2]), "r"(aF[3]),
                  "r"(bF[nt][0]), "r"(bF[nt][1]));
    }

    const float* mwin = mask + (size_t)(b & (NW - 1)) * (NTOK * NTOK);
    const int i0 = w * 16 + g;
    const int i1 = i0 + 8;
    float p0 = 0.f, p1 = 0.f;
    #pragma unroll
    for (int nt = 0; nt < 7; nt++) {
        #pragma unroll
        for (int v = 0; v < 4; v++) {
            int i = (v >= 2) ? i1 : i0;
            int j = nt * 8 + tig * 2 + (v & 1);
            float ev = 0.f;
            if (i < NTOK && j < NTOK) {
                int ij = i * NTOK + j;
                float bia = rel_table[rel_index[ij] * NHEAD + h];
                bia = fminf(fmaxf(bia, -5.f), 5.f);
                float val = c[nt][v] + mwin[ij] + bia;
                val = fminf(fmaxf(val, -10.f), 10.f);
                ev = __expf(val);
            }
            c[nt][v] = ev;
            if (v < 2) p0 += ev; else p1 += ev;
        }
    }
    p0 += __shfl_xor_sync(0xffffffffu, p0, 1);
    p0 += __shfl_xor_sync(0xffffffffu, p0, 2);
    p1 += __shfl_xor_sync(0xffffffffu, p1, 1);
    p1 += __shfl_xor_sync(0xffffffffu, p1, 2);

    __syncthreads();

    #pragma unroll
    for (int nt = 0; nt < 7; nt++) {
        #pragma unroll
        for (int v = 0; v < 4; v++) {
            int i = (v >= 2) ? i1 : i0;
            int j = nt * 8 + tig * 2 + (v & 1);
            Sb[i * SSTR + j] = f2tf(c[nt][v]);
        }
    }
    if (tig == 0) {
        rowsum[i0] = p0;
        rowsum[i1] = p1;
    }
    __syncthreads();

    float o[4][4] = {};
    #pragma unroll
    for (int ksi = 0; ksi < 7; ksi++) {
        uint32_t aF[4], bF[4][2];
        {
            int row = w * 16 + ((lane >> 3) & 1) * 8 + (lane & 7);
            int kof = ksi * 8 + (lane >> 4) * 4;
            uint32_t addr = (uint32_t)__cvta_generic_to_shared(Sb + row * SSTR + kof);
            asm volatile("ldmatrix.sync.aligned.m8n8.x4.shared.b16 {%0,%1,%2,%3}, [%4];"
                         : "=r"(aF[0]), "=r"(aF[1]), "=r"(aF[2]), "=r"(aF[3]) : "r"(addr));
        }
        #pragma unroll
        for (int nt = 0; nt < 4; nt++) {
            int row = nt * 8 + (lane & 7);
            int kof = ksi * 8 + ((lane >> 3) & 1) * 4;
            uint32_t addr = (uint32_t)__cvta_generic_to_shared(vT + row * SSTR + kof);
            asm volatile("ldmatrix.sync.aligned.m8n8.x2.shared.b16 {%0,%1}, [%2];"
                         : "=r"(bF[nt][0]), "=r"(bF[nt][1]) : "r"(addr));
        }
        #pragma unroll
        for (int nt = 0; nt < 4; nt++)
            asm volatile(
                "mma.sync.aligned.m16n8k8.row.col.f32.tf32.tf32.f32 "
                "{%0,%1,%2,%3}, {%4,%5,%6,%7}, {%8,%9}, {%0,%1,%2,%3};"
                : "+f"(o[nt][0]), "+f"(o[nt][1]), "+f"(o[nt][2]), "+f"(o[nt][3])
                : "r"(aF[0]), "r"(aF[1]), "r"(aF[2]), "r"(aF[3]),
                  "r"(bF[nt][0]), "r"(bF[nt][1]));
    }

    float inv0 = 1.f / rowsum[i0];
    float inv1 = 1.f / rowsum[i1];
    #pragma unroll
    for (int nt = 0; nt < 4; nt++) {
        int col = nt * 8 + tig * 2;
        if (i0 < NTOK)
            *(float2*)&out[(size_t)(b * NTOK + i0) * DIM + h * HD + col] =
                make_float2(o[nt][0] * inv0, o[nt][1] * inv0);
        if (i1 < NTOK)
            *(float2*)&out[(size_t)(b * NTOK + i1) * DIM + h * HD + col] =
                make_float2(o[nt][2] * inv1, o[nt][3] * inv1);
    }
}

// ---------------------------------------------------------------------------
// Launch
// ---------------------------------------------------------------------------
extern "C" void kernel_launch(void* const* d_in, const int* in_sizes, int n_in,
                              void* d_out, int out_size)
{
    const float* x = nullptr;
    const float* mask = nullptr;
    const float* qkv_w = nullptr;
    const float* qkv_b = nullptr;
    const float* proj_w = nullptr;
    const float* proj_b = nullptr;
    const float* rel_table = nullptr;
    const int*   rel_index = nullptr;

    for (int i = 0; i < n_in; i++) {
        switch (in_sizes[i]) {
            case 77070336: x         = (const float*)d_in[i]; break;
            case 614656:   mask      = (const float*)d_in[i]; break;
            case 442368:   qkv_w     = (const float*)d_in[i]; break;
            case 1152:     qkv_b     = (const float*)d_in[i]; break;
            case 147456:   proj_w    = (const float*)d_in[i]; break;
            case 384:      proj_b    = (const float*)d_in[i]; break;
            case 2028:     rel_table = (const float*)d_in[i]; break;
            case 2401:     rel_index = (const int*)d_in[i];   break;
            default: break;
        }
    }

    float* qkv_s = nullptr;
    float* att_s = nullptr;
    float* qkvwT = nullptr;
    float* projwT = nullptr;
    cudaGetSymbolAddress((void**)&qkv_s,  g_qkv);
    cudaGetSymbolAddress((void**)&att_s,  g_att);
    cudaGetSymbolAddress((void**)&qkvwT,  g_qkvwT);
    cudaGetSymbolAddress((void**)&projwT, g_projwT);

    cudaFuncSetAttribute(tf32_gemm_v2, cudaFuncAttributeMaxDynamicSharedMemorySize, SMEM_BYTES_V2);

    // 0) Transpose weights (tiny)
    dim3 tt(32, 32);
    transpose_kernel<<<dim3(QKV_N / 32, DIM / 32), tt>>>(qkv_w, qkvwT, DIM, QKV_N);
    transpose_kernel<<<dim3(DIM / 32, DIM / 32), tt>>>(proj_w, projwT, DIM, DIM);

    // 1) QKV GEMM
    dim3 g1(QKV_N / 128, M_ROWS / 128);
    tf32_gemm_v2<<<g1, 256, SMEM_BYTES_V2>>>(x, qkvwT, qkv_b, qkv_s, M_ROWS, QKV_N, DIM);

    // 2) Fused-softmax tensor-core attention
    dim3 g2(BW, NHEAD);
    attn_mma_kernel<<<g2, 128>>>(qkv_s, mask, rel_table, rel_index, att_s);

    // 3) Proj GEMM -> d_out
    dim3 g3(DIM / 128, M_ROWS / 128);
    tf32_gemm_v2<<<g3, 256, SMEM_BYTES_V2>>>(att_s, projwT, proj_b, (float*)d_out, M_ROWS, DIM, DIM);
}

// round 15
// speedup vs baseline: 2.0554x; 1.0523x over previous
#include <cuda_runtime.h>
#include <cuda_bf16.h>
#include <math.h>
#include <stdint.h>

// ---------------------------------------------------------------------------
// WindowAttention: cp.async tf32 GEMMs + single-barrier shuffle-P attention
// ---------------------------------------------------------------------------

#define BW      4096
#define NTOK    49
#define DIM     384
#define NHEAD   12
#define HD      32
#define NW      256
#define M_ROWS  (BW * NTOK)        // 200704
#define QKV_N   (3 * DIM)          // 1152

__device__ float g_qkv[(size_t)M_ROWS * QKV_N];   // ~925 MB
__device__ float g_att[(size_t)M_ROWS * DIM];     // ~308 MB
__device__ float g_qkvwT[QKV_N * DIM];            // qkv_w^T  [1152,384]
__device__ float g_projwT[DIM * DIM];             // proj_w^T [384,384]

__device__ __forceinline__ float f2tf(float x) {
    uint32_t r;
    asm("cvt.rna.tf32.f32 %0, %1;" : "=r"(r) : "f"(x));
    return __uint_as_float(r);
}
__device__ __forceinline__ uint32_t u2tf(uint32_t x) {
    uint32_t r;
    asm("cvt.rna.tf32.f32 %0, %1;" : "=r"(r) : "f"(__uint_as_float(x)));
    return r;
}

// ---------------------------------------------------------------------------
// Weight transpose: out[N][K] = in[K][N]. K,N multiples of 32.
// ---------------------------------------------------------------------------
__global__ void transpose_kernel(const float* __restrict__ in, float* __restrict__ out,
                                 int K, int N)
{
    __shared__ float t[32][33];
    int n0 = blockIdx.x * 32, k0 = blockIdx.y * 32;
    t[threadIdx.y][threadIdx.x] = in[(size_t)(k0 + threadIdx.y) * N + n0 + threadIdx.x];
    __syncthreads();
    out[(size_t)(n0 + threadIdx.y) * K + k0 + threadIdx.x] = t[threadIdx.x][threadIdx.y];
}

// ---------------------------------------------------------------------------
// tf32 GEMM v2 (R11, known good): C = A[M,K] @ Bt[N,K]^T + bias
// 128x128x32 tile, 256 thr, warp 64x32, 3-stage cp.async pipeline.
// ---------------------------------------------------------------------------
#define ASTR 36
#define STAGES 3
#define STAGE_FLOATS (2 * 128 * ASTR)
#define SMEM_BYTES_V2 (STAGES * STAGE_FLOATS * 4)     // 110592

__global__ __launch_bounds__(256, 2)
void tf32_gemm_v2(const float* __restrict__ A, const float* __restrict__ Bt,
                  const float* __restrict__ bias, float* __restrict__ C,
                  int M, int N, int K)
{
    const int tid  = threadIdx.x;
    const int lane = tid & 31;
    const int wid  = tid >> 5;
    const int warpM = wid & 1;
    const int warpN = wid >> 1;
    const int g   = lane >> 2;
    const int tig = lane & 3;

    const int bn = blockIdx.x * 128;
    const int bm = blockIdx.y * 128;

    extern __shared__ float sm[];

    const float* Agb = A  + (size_t)bm * K;
    const float* Bgb = Bt + (size_t)bn * K;

    auto issue_tile = [&](int kt, int s) {
        const float* Ag = Agb + kt * 32;
        const float* Bg = Bgb + kt * 32;
        float* As = sm + s * STAGE_FLOATS;
        float* Bs = As + 128 * ASTR;
        #pragma unroll
        for (int i = 0; i < 4; i++) {
            int c   = tid + 256 * i;
            int row = c >> 3;
            int kof = (c & 7) * 4;
            uint32_t sa = (uint32_t)__cvta_generic_to_shared(As + row * ASTR + kof);
            asm volatile("cp.async.cg.shared.global [%0], [%1], 16;"
                         :: "r"(sa), "l"(Ag + (size_t)row * K + kof));
            uint32_t sb = (uint32_t)__cvta_generic_to_shared(Bs + row * ASTR + kof);
            asm volatile("cp.async.cg.shared.global [%0], [%1], 16;"
                         :: "r"(sb), "l"(Bg + (size_t)row * K + kof));
        }
        asm volatile("cp.async.commit_group;");
    };

    const int nT = K / 32;

    issue_tile(0, 0);
    if (nT > 1) issue_tile(1, 1);

    float c[4][4][4] = {};

    for (int kt = 0; kt < nT; kt++) {
        if (kt + 1 < nT) asm volatile("cp.async.wait_group 1;");
        else             asm volatile("cp.async.wait_group 0;");
        __syncthreads();

        if (kt + 2 < nT) issue_tile(kt + 2, (kt + 2) % STAGES);

        const float* Ab = sm + (kt % STAGES) * STAGE_FLOATS;
        const float* Bb = Ab + 128 * ASTR;

        #pragma unroll
        for (int ks = 0; ks < 4; ks++) {
            uint32_t aF[4][4], bF[4][2];
            #pragma unroll
            for (int mt = 0; mt < 4; mt++) {
                int row = warpM * 64 + mt * 16 + ((lane >> 3) & 1) * 8 + (lane & 7);
                int kof = ks * 8 + (lane >> 4) * 4;
                uint32_t addr = (uint32_t)__cvta_generic_to_shared(Ab + row * ASTR + kof);
                asm volatile("ldmatrix.sync.aligned.m8n8.x4.shared.b16 {%0,%1,%2,%3}, [%4];"
                             : "=r"(aF[mt][0]), "=r"(aF[mt][1]), "=r"(aF[mt][2]), "=r"(aF[mt][3])
                             : "r"(addr));
                aF[mt][0] = u2tf(aF[mt][0]); aF[mt][1] = u2tf(aF[mt][1]);
                aF[mt][2] = u2tf(aF[mt][2]); aF[mt][3] = u2tf(aF[mt][3]);
            }
            #pragma unroll
            for (int nt = 0; nt < 4; nt++) {
                int row = warpN * 32 + nt * 8 + (lane & 7);
                int kof = ks * 8 + ((lane >> 3) & 1) * 4;
                uint32_t addr = (uint32_t)__cvta_generic_to_shared(Bb + row * ASTR + kof);
                asm volatile("ldmatrix.sync.aligned.m8n8.x2.shared.b16 {%0,%1}, [%2];"
                             : "=r"(bF[nt][0]), "=r"(bF[nt][1])
                             : "r"(addr));
                bF[nt][0] = u2tf(bF[nt][0]); bF[nt][1] = u2tf(bF[nt][1]);
            }
            #pragma unroll
            for (int mt = 0; mt < 4; mt++)
                #pragma unroll
                for (int nt = 0; nt < 4; nt++) {
                    asm volatile(
                        "mma.sync.aligned.m16n8k8.row.col.f32.tf32.tf32.f32 "
                        "{%0,%1,%2,%3}, {%4,%5,%6,%7}, {%8,%9}, {%0,%1,%2,%3};"
                        : "+f"(c[mt][nt][0]), "+f"(c[mt][nt][1]),
                          "+f"(c[mt][nt][2]), "+f"(c[mt][nt][3])
                        : "r"(aF[mt][0]), "r"(aF[mt][1]), "r"(aF[mt][2]), "r"(aF[mt][3]),
                          "r"(bF[nt][0]), "r"(bF[nt][1]));
                }
        }
        __syncthreads();
    }

    #pragma unroll
    for (int mt = 0; mt < 4; mt++) {
        #pragma unroll
        for (int nt = 0; nt < 4; nt++) {
            int row0 = bm + warpM * 64 + mt * 16 + g;
            int col  = bn + warpN * 32 + nt * 8 + tig * 2;
            float b0 = bias[col], b1 = bias[col + 1];
            float2 v0 = make_float2(c[mt][nt][0] + b0, c[mt][nt][1] + b1);
            float2 v1 = make_float2(c[mt][nt][2] + b0, c[mt][nt][3] + b1);
            *(float2*)&C[(size_t)row0 * N + col] = v0;
            *(float2*)&C[(size_t)(row0 + 8) * N + col] = v1;
        }
    }
}

// ---------------------------------------------------------------------------
// Attention v3: single barrier. S=qk^T (mma) -> fused mask/bias/clip/exp in
// registers -> quad-shuffle column permute builds P@V A-fragments directly
// from accumulators (no Sb smem, no second/third sync) -> O=P@V (mma) ->
// normalize at store with register-resident row sums.
// ---------------------------------------------------------------------------
#define SSTR 60

__global__ __launch_bounds__(128, 6)
void attn_mma_kernel(const float* __restrict__ qkv, const float* __restrict__ mask,
                     const float* __restrict__ rel_table, const int* __restrict__ rel_index,
                     float* __restrict__ out)
{
    const int b = blockIdx.x;
    const int h = blockIdx.y;
    const int tid  = threadIdx.x;
    const int lane = tid & 31;
    const int w    = tid >> 5;
    const int g    = lane >> 2;
    const int tig  = lane & 3;

    __shared__ float qs[64 * ASTR];
    __shared__ float ks[56 * ASTR];
    __shared__ float vT[HD * SSTR];

    const float scale = 0.1767766952966369f;

    // pad zeroing
    for (int idx = tid; idx < 15 * 32; idx += 128) {
        int r = 49 + (idx >> 5);
        qs[r * ASTR + (idx & 31)] = 0.f;
    }
    for (int idx = tid; idx < 7 * 32; idx += 128) {
        int r = 49 + (idx >> 5);
        ks[r * ASTR + (idx & 31)] = 0.f;
    }
    for (int idx = tid; idx < 32 * 7; idx += 128) {
        int d = idx / 7;
        vT[d * SSTR + 49 + (idx % 7)] = 0.f;
    }

    // stage q (scaled), k row-major; v transposed; all tf32
    for (int idx = tid; idx < NTOK * 8; idx += 128) {
        int i  = idx >> 3;
        int qd = (idx & 7) * 4;
        const float* base = qkv + (size_t)(b * NTOK + i) * QKV_N + h * HD + qd;
        float4 qv = *(const float4*)(base);
        float4 kv = *(const float4*)(base + DIM);
        float4 vv = *(const float4*)(base + 2 * DIM);
        *(float4*)(qs + i * ASTR + qd) =
            make_float4(f2tf(qv.x * scale), f2tf(qv.y * scale), f2tf(qv.z * scale), f2tf(qv.w * scale));
        *(float4*)(ks + i * ASTR + qd) =
            make_float4(f2tf(kv.x), f2tf(kv.y), f2tf(kv.z), f2tf(kv.w));
        vT[(qd + 0) * SSTR + i] = f2tf(vv.x);
        vT[(qd + 1) * SSTR + i] = f2tf(vv.y);
        vT[(qd + 2) * SSTR + i] = f2tf(vv.z);
        vT[(qd + 3) * SSTR + i] = f2tf(vv.w);
    }
    __syncthreads();   // the ONLY barrier

    // ---- S = q @ k^T : warp w -> rows [16w,16w+16), 7 n-tiles, 4 k-steps
    float c[7][4] = {};
    #pragma unroll
    for (int ksi = 0; ksi < 4; ksi++) {
        uint32_t aF[4], bF[7][2];
        {
            int row = w * 16 + ((lane >> 3) & 1) * 8 + (lane & 7);
            int kof = ksi * 8 + (lane >> 4) * 4;
            uint32_t addr = (uint32_t)__cvta_generic_to_shared(qs + row * ASTR + kof);
            asm volatile("ldmatrix.sync.aligned.m8n8.x4.shared.b16 {%0,%1,%2,%3}, [%4];"
                         : "=r"(aF[0]), "=r"(aF[1]), "=r"(aF[2]), "=r"(aF[3]) : "r"(addr));
        }
        #pragma unroll
        for (int nt = 0; nt < 7; nt++) {
            int row = nt * 8 + (lane & 7);
            int kof = ksi * 8 + ((lane >> 3) & 1) * 4;
            uint32_t addr = (uint32_t)__cvta_generic_to_shared(ks + row * ASTR + kof);
            asm volatile("ldmatrix.sync.aligned.m8n8.x2.shared.b16 {%0,%1}, [%2];"
                         : "=r"(bF[nt][0]), "=r"(bF[nt][1]) : "r"(addr));
        }
        #pragma unroll
        for (int nt = 0; nt < 7; nt++)
            asm volatile(
                "mma.sync.aligned.m16n8k8.row.col.f32.tf32.tf32.f32 "
                "{%0,%1,%2,%3}, {%4,%5,%6,%7}, {%8,%9}, {%0,%1,%2,%3};"
                : "+f"(c[nt][0]), "+f"(c[nt][1]), "+f"(c[nt][2]), "+f"(c[nt][3])
                : "r"(aF[0]), "r"(aF[1]), "r"(aF[2]), "r"(aF[3]),
                  "r"(bF[nt][0]), "r"(bF[nt][1]));
    }

    // ---- fused epilogue: +mask +clip(bias), clip(+-10), exp, row sums (regs)
    const float* mwin = mask + (size_t)(b & (NW - 1)) * (NTOK * NTOK);
    const int i0 = w * 16 + g;
    const int i1 = i0 + 8;
    float p0 = 0.f, p1 = 0.f;
    #pragma unroll
    for (int nt = 0; nt < 7; nt++) {
        #pragma unroll
        for (int v = 0; v < 4; v++) {
            int i = (v >= 2) ? i1 : i0;
            int j = nt * 8 + tig * 2 + (v & 1);
            float ev = 0.f;
            if (i < NTOK && j < NTOK) {
                int ij = i * NTOK + j;
                float bia = rel_table[rel_index[ij] * NHEAD + h];
                bia = fminf(fmaxf(bia, -5.f), 5.f);
                float val = c[nt][v] + mwin[ij] + bia;
                val = fminf(fmaxf(val, -10.f), 10.f);
                ev = __expf(val);
            }
            if (v < 2) p0 += ev; else p1 += ev;
            c[nt][v] = f2tf(ev);            // tf32-rounded prob (matches R11)
        }
    }
    p0 += __shfl_xor_sync(0xffffffffu, p0, 1);
    p0 += __shfl_xor_sync(0xffffffffu, p0, 2);
    p1 += __shfl_xor_sync(0xffffffffu, p1, 1);
    p1 += __shfl_xor_sync(0xffffffffu, p1, 2);

    // ---- O = P @ V : A-fragments built from accumulators via quad shuffles.
    // Accum layout: lane holds (rows g,g+8) x (cols 2*tig, 2*tig+1).
    // A-frag needs:  (rows g,g+8) x (cols tig, tig+4).
    const int src  = (lane & ~3) | (tig >> 1);   // holder of col (tig & ~1)
    const int src2 = src + 2;                    // holder of col ((tig+4) & ~1)
    const bool oddc = (tig & 1);

    float o[4][4] = {};
    #pragma unroll
    for (int ksi = 0; ksi < 7; ksi++) {
        float v00 = __shfl_sync(0xffffffffu, c[ksi][0], src);
        float v01 = __shfl_sync(0xffffffffu, c[ksi][1], src);
        float a0  = oddc ? v01 : v00;
        float v10 = __shfl_sync(0xffffffffu, c[ksi][2], src);
        float v11 = __shfl_sync(0xffffffffu, c[ksi][3], src);
        float a1  = oddc ? v11 : v10;
        float v20 = __shfl_sync(0xffffffffu, c[ksi][0], src2);
        float v21 = __shfl_sync(0xffffffffu, c[ksi][1], src2);
        float a2  = oddc ? v21 : v20;
        float v30 = __shfl_sync(0xffffffffu, c[ksi][2], src2);
        float v31 = __shfl_sync(0xffffffffu, c[ksi][3], src2);
        float a3  = oddc ? v31 : v30;

        uint32_t aF[4];
        aF[0] = __float_as_uint(a0);
        aF[1] = __float_as_uint(a1);
        aF[2] = __float_as_uint(a2);
        aF[3] = __float_as_uint(a3);

        uint32_t bF[4][2];
        #pragma unroll
        for (int nt = 0; nt < 4; nt++) {
            int row = nt * 8 + (lane & 7);
            int kof = ksi * 8 + ((lane >> 3) & 1) * 4;
            uint32_t addr = (uint32_t)__cvta_generic_to_shared(vT + row * SSTR + kof);
            asm volatile("ldmatrix.sync.aligned.m8n8.x2.shared.b16 {%0,%1}, [%2];"
                         : "=r"(bF[nt][0]), "=r"(bF[nt][1]) : "r"(addr));
        }
        #pragma unroll
        for (int nt = 0; nt < 4; nt++)
            asm volatile(
                "mma.sync.aligned.m16n8k8.row.col.f32.tf32.tf32.f32 "
                "{%0,%1,%2,%3}, {%4,%5,%6,%7}, {%8,%9}, {%0,%1,%2,%3};"
                : "+f"(o[nt][0]), "+f"(o[nt][1]), "+f"(o[nt][2]), "+f"(o[nt][3])
                : "r"(aF[0]), "r"(aF[1]), "r"(aF[2]), "r"(aF[3]),
                  "r"(bF[nt][0]), "r"(bF[nt][1]));
    }

    // ---- normalize at store (row sums live in registers, quad-uniform)
    float inv0 = 1.f / p0;
    float inv1 = 1.f / p1;
    #pragma unroll
    for (int nt = 0; nt < 4; nt++) {
        int col = nt * 8 + tig * 2;
        if (i0 < NTOK)
            *(float2*)&out[(size_t)(b * NTOK + i0) * DIM + h * HD + col] =
                make_float2(o[nt][0] * inv0, o[nt][1] * inv0);
        if (i1 < NTOK)
            *(float2*)&out[(size_t)(b * NTOK + i1) * DIM + h * HD + col] =
                make_float2(o[nt][2] * inv1, o[nt][3] * inv1);
    }
}

// ---------------------------------------------------------------------------
// Launch
// ---------------------------------------------------------------------------
extern "C" void kernel_launch(void* const* d_in, const int* in_sizes, int n_in,
                              void* d_out, int out_size)
{
    const float* x = nullptr;
    const float* mask = nullptr;
    const float* qkv_w = nullptr;
    const float* qkv_b = nullptr;
    const float* proj_w = nullptr;
    const float* proj_b = nullptr;
    const float* rel_table = nullptr;
    const int*   rel_index = nullptr;

    for (int i = 0; i < n_in; i++) {
        switch (in_sizes[i]) {
            case 77070336: x         = (const float*)d_in[i]; break;
            case 614656:   mask      = (const float*)d_in[i]; break;
            case 442368:   qkv_w     = (const float*)d_in[i]; break;
            case 1152:     qkv_b     = (const float*)d_in[i]; break;
            case 147456:   proj_w    = (const float*)d_in[i]; break;
            case 384:      proj_b    = (const float*)d_in[i]; break;
            case 2028:     rel_table = (const float*)d_in[i]; break;
            case 2401:     rel_index = (const int*)d_in[i];   break;
            default: break;
        }
    }

    float *qkv_s, *att_s, *qkvwT, *projwT;
    cudaGetSymbolAddress((void**)&qkv_s,  g_qkv);
    cudaGetSymbolAddress((void**)&att_s,  g_att);
    cudaGetSymbolAddress((void**)&qkvwT,  g_qkvwT);
    cudaGetSymbolAddress((void**)&projwT, g_projwT);

    cudaFuncSetAttribute(tf32_gemm_v2, cudaFuncAttributeMaxDynamicSharedMemorySize, SMEM_BYTES_V2);

    // 0) Transpose weights
    dim3 tt(32, 32);
    transpose_kernel<<<dim3(QKV_N / 32, DIM / 32), tt>>>(qkv_w, qkvwT, DIM, QKV_N);
    transpose_kernel<<<dim3(DIM / 32, DIM / 32), tt>>>(proj_w, projwT, DIM, DIM);

    // 1) QKV GEMM
    dim3 g1(QKV_N / 128, M_ROWS / 128);
    tf32_gemm_v2<<<g1, 256, SMEM_BYTES_V2>>>(x, qkvwT, qkv_b, qkv_s, M_ROWS, QKV_N, DIM);

    // 2) Attention (single-barrier, shuffle-P)
    dim3 g2(BW, NHEAD);
    attn_mma_kernel<<<g2, 128>>>(qkv_s, mask, rel_table, rel_index, att_s);

    // 3) Proj GEMM -> d_out
    dim3 g3(DIM / 128, M_ROWS / 128);
    tf32_gemm_v2<<<g3, 256, SMEM_BYTES_V2>>>(att_s, projwT, proj_b, (float*)d_out, M_ROWS, DIM, DIM);
}